// round 15
// baseline (speedup 1.0000x reference)
#include <cuda_runtime.h>
#include <cuda_bf16.h>
#include <math.h>
#include <stdint.h>
#include <cstdint>

#define HD    768
#define NB    4
#define SEQ   256
#define MROWS 1024        // NB*SEQ
#define NCOLS 3072        // 4 groups * HD
#define TOPK  4
#define NL    4
#define LOGITS_SZ (NB*SEQ*SEQ)   // 262144
#define NHCH  3
#define HCHUNK (HD/NHCH)         // 256

#define NEG_INF __int_as_float(0xff800000)

// ------------------------- device scratch (no allocs) -----------------------
__device__ float g_Ti[MROWS*HD];
__device__ float g_Tj[MROWS*HD];
__device__ float g_P [MROWS*HD];
__device__ float g_Q [MROWS*HD];
__device__ int   g_idx[MROWS*TOPK];
__device__ float g_part[NHCH * LOGITS_SZ];

// bf16 3-way splits of activations (A) and stacked weights (B)
__device__ __nv_bfloat16 g_A0[MROWS*HD], g_A1[MROWS*HD], g_A2[MROWS*HD];
__device__ __nv_bfloat16 g_B0[NCOLS*HD], g_B1[NCOLS*HD], g_B2[NCOLS*HD];

// ------------------------- small helpers ------------------------------------
__device__ __forceinline__ float frcp_(float x){ float r; asm("rcp.approx.f32 %0, %1;" : "=f"(r) : "f"(x)); return r; }
__device__ __forceinline__ float fex2_(float x){ float r; asm("ex2.approx.f32 %0, %1;" : "=f"(r) : "f"(x)); return r; }

// Accurate tanh independent of fast-math lowering; abs err ~3e-7
__device__ __forceinline__ float tanh_acc(float x){
    float ax = fabsf(x);
    float E  = fex2_(ax * 2.8853901f);      // 2*log2(e)
    float r  = frcp_(E + 1.0f);
    float y  = fmaf(-2.0f, r, 1.0f);
    return copysignf(y, x);
}

__device__ __forceinline__ uint32_t smem_u32(const void* p){
    uint32_t a;
    asm("{ .reg .u64 t; cvta.to.shared.u64 t, %1; cvt.u32.u64 %0, t; }" : "=r"(a) : "l"(p));
    return a;
}

__device__ __forceinline__ void cp16(uint32_t saddr, const void* g){
    asm volatile("cp.async.cg.shared.global [%0], [%1], 16;" :: "r"(saddr), "l"(g));
}
#define CP_COMMIT() asm volatile("cp.async.commit_group;" ::: "memory")
#define CP_WAIT1()  asm volatile("cp.async.wait_group 1;" ::: "memory")

__device__ __forceinline__ void ldsm4(uint32_t &r0, uint32_t &r1, uint32_t &r2, uint32_t &r3, uint32_t a){
    asm volatile("ldmatrix.sync.aligned.m8n8.x4.shared.b16 {%0,%1,%2,%3}, [%4];"
        : "=r"(r0), "=r"(r1), "=r"(r2), "=r"(r3) : "r"(a));
}

__device__ __forceinline__ void mma16816(float* d, const uint32_t* a, const uint32_t* b){
    asm volatile(
        "mma.sync.aligned.m16n8k16.row.col.f32.bf16.bf16.f32 "
        "{%0,%1,%2,%3}, {%4,%5,%6,%7}, {%8,%9}, {%0,%1,%2,%3};"
        : "+f"(d[0]), "+f"(d[1]), "+f"(d[2]), "+f"(d[3])
        : "r"(a[0]), "r"(a[1]), "r"(a[2]), "r"(a[3]), "r"(b[0]), "r"(b[1]));
}

// ---------------------------------------------------------------------------
// Prep: 3-way bf16 splits.
// ---------------------------------------------------------------------------
__global__ __launch_bounds__(256) void splitA_kernel(const float* __restrict__ X)
{
    int i = blockIdx.x * 256 + threadIdx.x;
    if (i >= MROWS*HD) return;
    float x = X[i];
    __nv_bfloat16 h = __float2bfloat16(x);
    float r1 = x - __bfloat162float(h);
    __nv_bfloat16 m = __float2bfloat16(r1);
    float r2 = r1 - __bfloat162float(m);
    g_A0[i] = h; g_A1[i] = m; g_A2[i] = __float2bfloat16(r2);
}

__global__ __launch_bounds__(256) void splitB_kernel(
    const float* __restrict__ Wa, const float* __restrict__ Ua,
    const float* __restrict__ Dw)
{
    int i = blockIdx.x * 256 + threadIdx.x;
    if (i >= NCOLS*HD) return;
    int n = i / HD, k = i - n * HD;
    float x;
    if      (n < 768)  x = Wa[n*HD + k];
    else if (n < 1536) x = Ua[(n-768)*HD + k];
    else if (n < 2304) x = Dw[(size_t)(n-1536)*(2*HD) + k];
    else               x = Dw[(size_t)(n-2304)*(2*HD) + HD + k];
    __nv_bfloat16 h = __float2bfloat16(x);
    float r1 = x - __bfloat162float(h);
    __nv_bfloat16 m = __float2bfloat16(r1);
    float r2 = r1 - __bfloat162float(m);
    g_B0[i] = h; g_B1[i] = m; g_B2[i] = __float2bfloat16(r2);
}

// ---------------------------------------------------------------------------
// mma.sync GEMM (unchanged): D[1024,3072] = sum of 6 split-products.
// ---------------------------------------------------------------------------
#define KB        32
#define NKCH      (HD / KB)        // 24
#define A_SPL_B   (128 * 80)
#define B_SPL_B   (64 * 80)
#define A_STG_B   (3 * A_SPL_B)
#define STG_B     (A_STG_B + 3 * B_SPL_B)
#define GEMM_SMEM (2 * STG_B)      // 92160

__global__ __launch_bounds__(256, 2) void gemm_mma_kernel(
    const float* __restrict__ Wab, const float* __restrict__ Uab,
    const float* __restrict__ Db)
{
    extern __shared__ char dsm[];
    const uint32_t sbase = smem_u32(dsm);

    const int tid  = threadIdx.x;
    const int wid  = tid >> 5;
    const int lane = tid & 31;
    const int wm   = wid >> 1;
    const int wn   = wid & 1;
    const int m0   = blockIdx.y * 128;
    const int n0   = blockIdx.x * 64;

    const __nv_bfloat16* Ap[3] = { g_A0, g_A1, g_A2 };
    const __nv_bfloat16* Bp[3] = { g_B0, g_B1, g_B2 };

    auto issue_stage = [&](int kc, int buf){
        const uint32_t sb = sbase + buf * STG_B;
        #pragma unroll
        for (int i = 0; i < 9; i++) {
            int o = tid + i * 256;
            if (o < 1536) {
                int s   = o >> 9;
                int rem = o & 511;
                int r   = rem >> 2, seg = rem & 3;
                const void* g = Ap[s] + ((size_t)(m0 + r) * HD + kc*KB + seg*8);
                cp16(sb + s*A_SPL_B + r*80 + seg*16, g);
            } else {
                int o2  = o - 1536;
                int s   = o2 >> 8;
                int rem = o2 & 255;
                int r   = rem >> 2, seg = rem & 3;
                const void* g = Bp[s] + ((size_t)(n0 + r) * HD + kc*KB + seg*8);
                cp16(sb + A_STG_B + s*B_SPL_B + r*80 + seg*16, g);
            }
        }
        CP_COMMIT();
    };

    float acc[2][4][4];
    #pragma unroll
    for (int mt = 0; mt < 2; mt++)
        #pragma unroll
        for (int nt = 0; nt < 4; nt++)
            #pragma unroll
            for (int c = 0; c < 4; c++) acc[mt][nt][c] = 0.0f;

    issue_stage(0, 0);
    issue_stage(1, 1);

    const int SI[6] = {0,0,1,0,1,2};
    const int SJ[6] = {0,1,0,2,1,0};

    const int a_row = wm*32 + (lane & 15);
    const int a_cb  = (lane >> 4) * 16;
    const int b_row = wn*32 + ((lane >> 4) & 1)*8 + (lane & 7);
    const int b_cb  = ((lane >> 3) & 1) * 16;

    for (int kc = 0; kc < NKCH; kc++) {
        CP_WAIT1();
        __syncthreads();
        const uint32_t sb = sbase + (kc & 1) * STG_B;

        #pragma unroll
        for (int ks = 0; ks < 2; ks++) {
            const uint32_t kbyte = ks*32;
            uint32_t afr[3][2][4];
            uint32_t bfr[3][4][2];
            #pragma unroll
            for (int s = 0; s < 3; s++) {
                #pragma unroll
                for (int mt = 0; mt < 2; mt++) {
                    uint32_t ad = sb + s*A_SPL_B + (a_row + mt*16)*80 + kbyte + a_cb;
                    ldsm4(afr[s][mt][0], afr[s][mt][1], afr[s][mt][2], afr[s][mt][3], ad);
                }
                #pragma unroll
                for (int pr = 0; pr < 2; pr++) {
                    uint32_t bd = sb + A_STG_B + s*B_SPL_B + (b_row + pr*16)*80 + kbyte + b_cb;
                    ldsm4(bfr[s][pr*2][0], bfr[s][pr*2][1],
                          bfr[s][pr*2+1][0], bfr[s][pr*2+1][1], bd);
                }
            }
            #pragma unroll
            for (int p = 0; p < 6; p++) {
                const int si = SI[p], sj = SJ[p];
                #pragma unroll
                for (int mt = 0; mt < 2; mt++)
                    #pragma unroll
                    for (int nt = 0; nt < 4; nt++)
                        mma16816(acc[mt][nt], afr[si][mt], bfr[sj][nt]);
            }
        }

        __syncthreads();
        if (kc + 2 < NKCH) issue_stage(kc + 2, kc & 1);
    }

    const int group = blockIdx.x / 12;
    const int ng0   = (blockIdx.x % 12) * 64;

    float* dst; const float* bias; int do_tanh;
    if      (group == 0){ dst = g_Ti; bias = Wab; do_tanh = 1; }
    else if (group == 1){ dst = g_Tj; bias = Uab; do_tanh = 1; }
    else if (group == 2){ dst = g_P;  bias = Db;  do_tanh = 0; }
    else                { dst = g_Q;  bias = 0;   do_tanh = 0; }

    const int er = lane >> 2;
    const int ec = (lane & 3) * 2;

    #pragma unroll
    for (int mt = 0; mt < 2; mt++) {
        #pragma unroll
        for (int nt = 0; nt < 4; nt++) {
            const int c = ng0 + wn*32 + nt*8 + ec;
            float b0 = bias ? bias[c]     : 0.0f;
            float b1 = bias ? bias[c + 1] : 0.0f;
            #pragma unroll
            for (int half = 0; half < 2; half++) {
                const int m = m0 + wm*32 + mt*16 + er + half*8;
                float v0 = acc[mt][nt][half*2 + 0] + b0;
                float v1 = acc[mt][nt][half*2 + 1] + b1;
                if (do_tanh) { v0 = tanh_acc(v0); v1 = tanh_acc(v1); }
                float2 w = make_float2(v0, v1);
                *(float2*)&dst[(size_t)m * HD + c] = w;
            }
        }
    }
}

// ---------------------------------------------------------------------------
// Biaffine v4: lane owns one c column, 8 accumulators over a (more warps in
// flight than v3's 16). CTA: 32a x 32c over one h-chunk; warp w -> a in
// [w*8, w*8+8). hp loop fully unrolled -> immediate smem offsets.
// Combined fraction per h-pair:
//   d_k = 1 + ti_k*tj_k,  n_k = vi_k + vj_k (v pre-multiplied into t),
//   acc += (n2*d1 + n1*d2) * rcp(d1*d2)
// ---------------------------------------------------------------------------
__global__ __launch_bounds__(128) void biaffine4_kernel(const float* __restrict__ va)
{
    __shared__ float  sTi[32][17];
    __shared__ float  sVi[32][17];
    __shared__ float4 sAj[32][8];

    const int tid  = threadIdx.x;
    const int wid  = tid >> 5;
    const int lane = tid & 31;
    const int bz   = blockIdx.z;          // b*NHCH + hc
    const int b    = bz / NHCH;
    const int hc   = bz - b * NHCH;
    const int c0   = blockIdx.x * 32;
    const int a0   = blockIdx.y * 32;
    const int aw   = wid * 8;

    const float* TiB = g_Ti + (size_t)(b*SEQ + c0) * HD;
    const float* TjB = g_Tj + (size_t)(b*SEQ + a0) * HD;

    float acc[8];
    #pragma unroll
    for (int i = 0; i < 8; i++) acc[i] = 0.0f;

    for (int ch = 0; ch < HCHUNK/16; ch++) {
        const int k0 = hc*HCHUNK + ch*16;

        // stage c-side: 32 rows x 16 h (1 float4 per thread)
        {
            const int row = tid >> 2, seg = tid & 3;
            float4 t = *(const float4*)&TiB[(size_t)row*HD + k0 + seg*4];
            float4 v = *(const float4*)&va[k0 + seg*4];
            sTi[row][seg*4+0] = t.x; sTi[row][seg*4+1] = t.y;
            sTi[row][seg*4+2] = t.z; sTi[row][seg*4+3] = t.w;
            sVi[row][seg*4+0] = t.x*v.x; sVi[row][seg*4+1] = t.y*v.y;
            sVi[row][seg*4+2] = t.z*v.z; sVi[row][seg*4+3] = t.w*v.w;
        }
        // stage a-side: 32 rows x 8 h-pairs (2 entries per thread)
        #pragma unroll
        for (int it = 0; it < 2; it++) {
            const int id  = tid + it*128;
            const int row = id >> 3, hp = id & 7;
            float2 t = *(const float2*)&TjB[(size_t)row*HD + k0 + hp*2];
            float2 v = *(const float2*)&va[k0 + hp*2];
            sAj[row][hp] = make_float4(t.x, t.y, t.x*v.x, t.y*v.y);
        }
        __syncthreads();

        #pragma unroll
        for (int hp = 0; hp < 8; hp++) {
            const float ti0 = sTi[lane][2*hp];
            const float ti1 = sTi[lane][2*hp+1];
            const float vi0 = sVi[lane][2*hp];
            const float vi1 = sVi[lane][2*hp+1];
            #pragma unroll
            for (int a = 0; a < 8; a++) {
                const float4 f = sAj[aw + a][hp];
                const float d1 = fmaf(ti0, f.x, 1.0f);
                const float d2 = fmaf(ti1, f.y, 1.0f);
                const float n1 = vi0 + f.z;
                const float n2 = vi1 + f.w;
                const float num = fmaf(n2, d1, n1*d2);
                acc[a] = fmaf(num, frcp_(d1*d2), acc[a]);
            }
        }
        __syncthreads();
    }

    float* pdst = g_part + (size_t)hc * LOGITS_SZ;
    #pragma unroll
    for (int a = 0; a < 8; a++)
        pdst[((size_t)(b*SEQ + a0 + aw + a)) * SEQ + c0 + lane] = acc[a];
}

// ---------------------------------------------------------------------------
// Top-4 per row; sums the 3 h-chunk partials and writes final logits.
// ---------------------------------------------------------------------------
__global__ __launch_bounds__(256) void topk_kernel(float* __restrict__ out)
{
    const int row  = blockIdx.x * 8 + (threadIdx.x >> 5);
    const int lane = threadIdx.x & 31;
    const size_t base = (size_t)row * SEQ;

    float v[8];
    #pragma unroll
    for (int j = 0; j < 8; j++) {
        const size_t o = base + j*32 + lane;
        float s = g_part[o] + g_part[LOGITS_SZ + o] + g_part[2*LOGITS_SZ + o];
        out[o] = s;
        v[j] = s;
    }

    #pragma unroll
    for (int k = 0; k < TOPK; k++) {
        float bv = NEG_INF; int bi = 1 << 30;
        #pragma unroll
        for (int j = 0; j < 8; j++) {
            const int idx = j*32 + lane;
            if (v[j] > bv || (v[j] == bv && idx < bi)) { bv = v[j]; bi = idx; }
        }
        #pragma unroll
        for (int off = 16; off > 0; off >>= 1) {
            float ov = __shfl_down_sync(0xffffffffu, bv, off);
            int   oi = __shfl_down_sync(0xffffffffu, bi, off);
            if (ov > bv || (ov == bv && oi < bi)) { bv = ov; bi = oi; }
        }
        bi = __shfl_sync(0xffffffffu, bi, 0);
        if (lane == 0) g_idx[row*TOPK + k] = bi;
        if ((bi & 31) == lane) {
            const int slot = bi >> 5;
            #pragma unroll
            for (int j = 0; j < 8; j++) if (j == slot) v[j] = NEG_INF;
        }
    }
}

// ---------------------------------------------------------------------------
// Type logits: hidden = tanh(P[row] + Q[head]);  out = hidden @ fc_w^T + fc_b
// ---------------------------------------------------------------------------
__global__ __launch_bounds__(128) void typelogits_kernel(
    const float* __restrict__ fw, const float* __restrict__ fb,
    float* __restrict__ out)
{
    const int row  = blockIdx.x;
    const int m    = threadIdx.x >> 5;
    const int lane = threadIdx.x & 31;
    const int b    = row >> 8;

    const int hidx = g_idx[row*TOPK + m];
    const float* Prow = g_P + (size_t)row * HD;
    const float* Qrow = g_Q + (size_t)(b*SEQ + hidx) * HD;

    float a0=0.f, a1=0.f, a2=0.f, a3=0.f;
    for (int h = lane; h < HD; h += 32) {
        const float t = tanh_acc(Prow[h] + Qrow[h]);
        a0 = fmaf(t, fw[h       ], a0);
        a1 = fmaf(t, fw[h +   HD], a1);
        a2 = fmaf(t, fw[h + 2*HD], a2);
        a3 = fmaf(t, fw[h + 3*HD], a3);
    }
    #pragma unroll
    for (int off = 16; off > 0; off >>= 1) {
        a0 += __shfl_down_sync(0xffffffffu, a0, off);
        a1 += __shfl_down_sync(0xffffffffu, a1, off);
        a2 += __shfl_down_sync(0xffffffffu, a2, off);
        a3 += __shfl_down_sync(0xffffffffu, a3, off);
    }
    if (lane == 0) {
        float* o = out + LOGITS_SZ + (size_t)(row*TOPK + m) * NL;
        o[0] = a0 + fb[0];
        o[1] = a1 + fb[1];
        o[2] = a2 + fb[2];
        o[3] = a3 + fb[3];
    }
}

// ---------------------------------------------------------------------------
extern "C" void kernel_launch(void* const* d_in, const int* in_sizes, int n_in,
                              void* d_out, int out_size)
{
    const float* X   = (const float*)d_in[0];
    const float* Wa  = (const float*)d_in[1];
    const float* Wab = (const float*)d_in[2];
    const float* Ua  = (const float*)d_in[3];
    const float* Uab = (const float*)d_in[4];
    const float* va  = (const float*)d_in[5];
    const float* Dw  = (const float*)d_in[6];
    const float* Db  = (const float*)d_in[7];
    const float* fw  = (const float*)d_in[8];
    const float* fb  = (const float*)d_in[9];
    float* out = (float*)d_out;

    cudaFuncSetAttribute(gemm_mma_kernel,
                         cudaFuncAttributeMaxDynamicSharedMemorySize, GEMM_SMEM);

    splitA_kernel<<<(MROWS*HD + 255)/256, 256>>>(X);
    splitB_kernel<<<(NCOLS*HD + 255)/256, 256>>>(Wa, Ua, Dw);

    dim3 gg(NCOLS/64, MROWS/128);            // 48 x 8 = 384 CTAs
    gemm_mma_kernel<<<gg, 256, GEMM_SMEM>>>(Wab, Uab, Db);

    dim3 g2(SEQ/32, SEQ/32, NB*NHCH);        // 8 x 8 x 12 = 768 CTAs
    biaffine4_kernel<<<g2, 128>>>(va);

    topk_kernel<<<MROWS/8, 256>>>(out);

    typelogits_kernel<<<MROWS, 128>>>(fw, fb, out);
}

// round 17
// speedup vs baseline: 1.1552x; 1.1552x over previous
#include <cuda_runtime.h>
#include <cuda_bf16.h>
#include <math.h>
#include <stdint.h>
#include <cstdint>

#define HD    768
#define NB    4
#define SEQ   256
#define MROWS 1024        // NB*SEQ
#define NCOLS 3072        // 4 groups * HD
#define TOPK  4
#define NL    4
#define LOGITS_SZ (NB*SEQ*SEQ)   // 262144
#define NHCH  3
#define HCHUNK (HD/NHCH)         // 256

#define NEG_INF __int_as_float(0xff800000)

// ------------------------- device scratch (no allocs) -----------------------
// NOTE: g_Ti/g_Tj now hold E = exp(2*h) (exponential-form biaffine).
__device__ float g_Ti[MROWS*HD];
__device__ float g_Tj[MROWS*HD];
__device__ float g_P [MROWS*HD];
__device__ float g_Q [MROWS*HD];
__device__ int   g_idx[MROWS*TOPK];
__device__ float g_part[NHCH * LOGITS_SZ];

// bf16 3-way splits of activations (A) and stacked weights (B)
__device__ __nv_bfloat16 g_A0[MROWS*HD], g_A1[MROWS*HD], g_A2[MROWS*HD];
__device__ __nv_bfloat16 g_B0[NCOLS*HD], g_B1[NCOLS*HD], g_B2[NCOLS*HD];

// ------------------------- small helpers ------------------------------------
__device__ __forceinline__ float frcp_(float x){ float r; asm("rcp.approx.f32 %0, %1;" : "=f"(r) : "f"(x)); return r; }
__device__ __forceinline__ float fex2_(float x){ float r; asm("ex2.approx.f32 %0, %1;" : "=f"(r) : "f"(x)); return r; }

// Accurate tanh independent of fast-math lowering; abs err ~3e-7
__device__ __forceinline__ float tanh_acc(float x){
    float ax = fabsf(x);
    float E  = fex2_(ax * 2.8853901f);      // 2*log2(e)
    float r  = frcp_(E + 1.0f);
    float y  = fmaf(-2.0f, r, 1.0f);
    return copysignf(y, x);
}

__device__ __forceinline__ uint32_t smem_u32(const void* p){
    uint32_t a;
    asm("{ .reg .u64 t; cvta.to.shared.u64 t, %1; cvt.u32.u64 %0, t; }" : "=r"(a) : "l"(p));
    return a;
}

__device__ __forceinline__ void cp16(uint32_t saddr, const void* g){
    asm volatile("cp.async.cg.shared.global [%0], [%1], 16;" :: "r"(saddr), "l"(g));
}
#define CP_COMMIT() asm volatile("cp.async.commit_group;" ::: "memory")
#define CP_WAIT1()  asm volatile("cp.async.wait_group 1;" ::: "memory")

__device__ __forceinline__ void ldsm4(uint32_t &r0, uint32_t &r1, uint32_t &r2, uint32_t &r3, uint32_t a){
    asm volatile("ldmatrix.sync.aligned.m8n8.x4.shared.b16 {%0,%1,%2,%3}, [%4];"
        : "=r"(r0), "=r"(r1), "=r"(r2), "=r"(r3) : "r"(a));
}

__device__ __forceinline__ void mma16816(float* d, const uint32_t* a, const uint32_t* b){
    asm volatile(
        "mma.sync.aligned.m16n8k16.row.col.f32.bf16.bf16.f32 "
        "{%0,%1,%2,%3}, {%4,%5,%6,%7}, {%8,%9}, {%0,%1,%2,%3};"
        : "+f"(d[0]), "+f"(d[1]), "+f"(d[2]), "+f"(d[3])
        : "r"(a[0]), "r"(a[1]), "r"(a[2]), "r"(a[3]), "r"(b[0]), "r"(b[1]));
}

// ---------------------------------------------------------------------------
// Prep: 3-way bf16 splits.
// ---------------------------------------------------------------------------
__global__ __launch_bounds__(256) void splitA_kernel(const float* __restrict__ X)
{
    int i = blockIdx.x * 256 + threadIdx.x;
    if (i >= MROWS*HD) return;
    float x = X[i];
    __nv_bfloat16 h = __float2bfloat16(x);
    float r1 = x - __bfloat162float(h);
    __nv_bfloat16 m = __float2bfloat16(r1);
    float r2 = r1 - __bfloat162float(m);
    g_A0[i] = h; g_A1[i] = m; g_A2[i] = __float2bfloat16(r2);
}

__global__ __launch_bounds__(256) void splitB_kernel(
    const float* __restrict__ Wa, const float* __restrict__ Ua,
    const float* __restrict__ Dw)
{
    int i = blockIdx.x * 256 + threadIdx.x;
    if (i >= NCOLS*HD) return;
    int n = i / HD, k = i - n * HD;
    float x;
    if      (n < 768)  x = Wa[n*HD + k];
    else if (n < 1536) x = Ua[(n-768)*HD + k];
    else if (n < 2304) x = Dw[(size_t)(n-1536)*(2*HD) + k];
    else               x = Dw[(size_t)(n-2304)*(2*HD) + HD + k];
    __nv_bfloat16 h = __float2bfloat16(x);
    float r1 = x - __bfloat162float(h);
    __nv_bfloat16 m = __float2bfloat16(r1);
    float r2 = r1 - __bfloat162float(m);
    g_B0[i] = h; g_B1[i] = m; g_B2[i] = __float2bfloat16(r2);
}

// ---------------------------------------------------------------------------
// mma.sync GEMM: D[1024,3072] = sum of 6 split-products.
// Epilogue groups 0/1 now store E = exp(2*(h+bias)) for the biaffine.
// ---------------------------------------------------------------------------
#define KB        32
#define NKCH      (HD / KB)        // 24
#define A_SPL_B   (128 * 80)
#define B_SPL_B   (64 * 80)
#define A_STG_B   (3 * A_SPL_B)
#define STG_B     (A_STG_B + 3 * B_SPL_B)
#define GEMM_SMEM (2 * STG_B)      // 92160

__global__ __launch_bounds__(256, 2) void gemm_mma_kernel(
    const float* __restrict__ Wab, const float* __restrict__ Uab,
    const float* __restrict__ Db)
{
    extern __shared__ char dsm[];
    const uint32_t sbase = smem_u32(dsm);

    const int tid  = threadIdx.x;
    const int wid  = tid >> 5;
    const int lane = tid & 31;
    const int wm   = wid >> 1;
    const int wn   = wid & 1;
    const int m0   = blockIdx.y * 128;
    const int n0   = blockIdx.x * 64;

    const __nv_bfloat16* Ap[3] = { g_A0, g_A1, g_A2 };
    const __nv_bfloat16* Bp[3] = { g_B0, g_B1, g_B2 };

    auto issue_stage = [&](int kc, int buf){
        const uint32_t sb = sbase + buf * STG_B;
        #pragma unroll
        for (int i = 0; i < 9; i++) {
            int o = tid + i * 256;
            if (o < 1536) {
                int s   = o >> 9;
                int rem = o & 511;
                int r   = rem >> 2, seg = rem & 3;
                const void* g = Ap[s] + ((size_t)(m0 + r) * HD + kc*KB + seg*8);
                cp16(sb + s*A_SPL_B + r*80 + seg*16, g);
            } else {
                int o2  = o - 1536;
                int s   = o2 >> 8;
                int rem = o2 & 255;
                int r   = rem >> 2, seg = rem & 3;
                const void* g = Bp[s] + ((size_t)(n0 + r) * HD + kc*KB + seg*8);
                cp16(sb + A_STG_B + s*B_SPL_B + r*80 + seg*16, g);
            }
        }
        CP_COMMIT();
    };

    float acc[2][4][4];
    #pragma unroll
    for (int mt = 0; mt < 2; mt++)
        #pragma unroll
        for (int nt = 0; nt < 4; nt++)
            #pragma unroll
            for (int c = 0; c < 4; c++) acc[mt][nt][c] = 0.0f;

    issue_stage(0, 0);
    issue_stage(1, 1);

    const int SI[6] = {0,0,1,0,1,2};
    const int SJ[6] = {0,1,0,2,1,0};

    const int a_row = wm*32 + (lane & 15);
    const int a_cb  = (lane >> 4) * 16;
    const int b_row = wn*32 + ((lane >> 4) & 1)*8 + (lane & 7);
    const int b_cb  = ((lane >> 3) & 1) * 16;

    for (int kc = 0; kc < NKCH; kc++) {
        CP_WAIT1();
        __syncthreads();
        const uint32_t sb = sbase + (kc & 1) * STG_B;

        #pragma unroll
        for (int ks = 0; ks < 2; ks++) {
            const uint32_t kbyte = ks*32;
            uint32_t afr[3][2][4];
            uint32_t bfr[3][4][2];
            #pragma unroll
            for (int s = 0; s < 3; s++) {
                #pragma unroll
                for (int mt = 0; mt < 2; mt++) {
                    uint32_t ad = sb + s*A_SPL_B + (a_row + mt*16)*80 + kbyte + a_cb;
                    ldsm4(afr[s][mt][0], afr[s][mt][1], afr[s][mt][2], afr[s][mt][3], ad);
                }
                #pragma unroll
                for (int pr = 0; pr < 2; pr++) {
                    uint32_t bd = sb + A_STG_B + s*B_SPL_B + (b_row + pr*16)*80 + kbyte + b_cb;
                    ldsm4(bfr[s][pr*2][0], bfr[s][pr*2][1],
                          bfr[s][pr*2+1][0], bfr[s][pr*2+1][1], bd);
                }
            }
            #pragma unroll
            for (int p = 0; p < 6; p++) {
                const int si = SI[p], sj = SJ[p];
                #pragma unroll
                for (int mt = 0; mt < 2; mt++)
                    #pragma unroll
                    for (int nt = 0; nt < 4; nt++)
                        mma16816(acc[mt][nt], afr[si][mt], bfr[sj][nt]);
            }
        }

        __syncthreads();
        if (kc + 2 < NKCH) issue_stage(kc + 2, kc & 1);
    }

    const int group = blockIdx.x / 12;
    const int ng0   = (blockIdx.x % 12) * 64;

    float* dst; const float* bias; int do_exp;
    if      (group == 0){ dst = g_Ti; bias = Wab; do_exp = 1; }
    else if (group == 1){ dst = g_Tj; bias = Uab; do_exp = 1; }
    else if (group == 2){ dst = g_P;  bias = Db;  do_exp = 0; }
    else                { dst = g_Q;  bias = 0;   do_exp = 0; }

    const int er = lane >> 2;
    const int ec = (lane & 3) * 2;

    #pragma unroll
    for (int mt = 0; mt < 2; mt++) {
        #pragma unroll
        for (int nt = 0; nt < 4; nt++) {
            const int c = ng0 + wn*32 + nt*8 + ec;
            float b0 = bias ? bias[c]     : 0.0f;
            float b1 = bias ? bias[c + 1] : 0.0f;
            #pragma unroll
            for (int half = 0; half < 2; half++) {
                const int m = m0 + wm*32 + mt*16 + er + half*8;
                float v0 = acc[mt][nt][half*2 + 0] + b0;
                float v1 = acc[mt][nt][half*2 + 1] + b1;
                if (do_exp) {
                    v0 = fex2_(v0 * 2.8853901f);   // E = exp(2*h) = 2^(2*log2(e)*h)
                    v1 = fex2_(v1 * 2.8853901f);
                }
                float2 w = make_float2(v0, v1);
                *(float2*)&dst[(size_t)m * HD + c] = w;
            }
        }
    }
}

// ---------------------------------------------------------------------------
// Biaffine v5 (exponential form):
//   tanh(hi+hj) = 1 - 2/(1 + Ei*Ej),  Ei = exp(2*hi) precomputed in epilogue.
//   logit = Vsum - 2 * sum_h v_h / (1 + Ei*Ej)
// Reciprocal sums combined 4 h per rcp via 2-level fraction tree:
//   Dk = 1 + Ei_k*Ej_k ; d12 = D1*D2 ; n12 = v1*D2 + v2*D1 (= v1/D1+v2/D2 over d12)
//   quad = (n12*d34 + n34*d12) / (d12*d34)
// Lane owns one c; 8 a-accumulators; CTA 32a x 32c x one h-chunk of 256.
// ---------------------------------------------------------------------------
__global__ __launch_bounds__(128) void biaffine5_kernel(const float* __restrict__ va)
{
    __shared__ float  sEi[32][20];    // stride 20 floats: LDS.128 conflict-free
    __shared__ float4 sAj[32][4];     // [a][h-quad], broadcast reads
    __shared__ float  sV[16];

    const int tid  = threadIdx.x;
    const int wid  = tid >> 5;
    const int lane = tid & 31;
    const int bz   = blockIdx.z;          // b*NHCH + hc
    const int b    = bz / NHCH;
    const int hc   = bz - b * NHCH;
    const int c0   = blockIdx.x * 32;
    const int a0   = blockIdx.y * 32;
    const int aw   = wid * 8;

    const float* EiB = g_Ti + (size_t)(b*SEQ + c0) * HD;
    const float* EjB = g_Tj + (size_t)(b*SEQ + a0) * HD;

    float acc[8];
    #pragma unroll
    for (int i = 0; i < 8; i++) acc[i] = 0.0f;
    float vs = 0.0f;

    for (int ch = 0; ch < HCHUNK/16; ch++) {
        const int k0 = hc*HCHUNK + ch*16;
        {
            const int row = tid >> 2, q = tid & 3;
            float4 ei = *(const float4*)&EiB[(size_t)row*HD + k0 + q*4];
            *(float4*)&sEi[row][q*4] = ei;
            float4 ej = *(const float4*)&EjB[(size_t)row*HD + k0 + q*4];
            sAj[row][q] = ej;
            if (tid < 4) *(float4*)&sV[tid*4] = *(const float4*)&va[k0 + tid*4];
        }
        __syncthreads();

        #pragma unroll
        for (int hq = 0; hq < 4; hq++) {
            const float4 ei = *(const float4*)&sEi[lane][hq*4];
            const float4 vv = *(const float4*)&sV[hq*4];
            vs += (vv.x + vv.y) + (vv.z + vv.w);
            #pragma unroll
            for (int a = 0; a < 8; a++) {
                const float4 f = sAj[aw + a][hq];
                const float D1 = fmaf(ei.x, f.x, 1.0f);
                const float D2 = fmaf(ei.y, f.y, 1.0f);
                const float D3 = fmaf(ei.z, f.z, 1.0f);
                const float D4 = fmaf(ei.w, f.w, 1.0f);
                const float d12 = D1*D2;
                const float d34 = D3*D4;
                const float n12 = fmaf(vv.y, D1, vv.x*D2);
                const float n34 = fmaf(vv.w, D3, vv.z*D4);
                const float num = fmaf(n34, d12, n12*d34);
                acc[a] = fmaf(num, frcp_(d12*d34), acc[a]);
            }
        }
        __syncthreads();
    }

    float* pdst = g_part + (size_t)hc * LOGITS_SZ;
    #pragma unroll
    for (int a = 0; a < 8; a++)
        pdst[((size_t)(b*SEQ + a0 + aw + a)) * SEQ + c0 + lane] =
            fmaf(-2.0f, acc[a], vs);
}

// ---------------------------------------------------------------------------
// Top-4 per row; sums the 3 h-chunk partials and writes final logits.
// ---------------------------------------------------------------------------
__global__ __launch_bounds__(256) void topk_kernel(float* __restrict__ out)
{
    const int row  = blockIdx.x * 8 + (threadIdx.x >> 5);
    const int lane = threadIdx.x & 31;
    const size_t base = (size_t)row * SEQ;

    float v[8];
    #pragma unroll
    for (int j = 0; j < 8; j++) {
        const size_t o = base + j*32 + lane;
        float s = g_part[o] + g_part[LOGITS_SZ + o] + g_part[2*LOGITS_SZ + o];
        out[o] = s;
        v[j] = s;
    }

    #pragma unroll
    for (int k = 0; k < TOPK; k++) {
        float bv = NEG_INF; int bi = 1 << 30;
        #pragma unroll
        for (int j = 0; j < 8; j++) {
            const int idx = j*32 + lane;
            if (v[j] > bv || (v[j] == bv && idx < bi)) { bv = v[j]; bi = idx; }
        }
        #pragma unroll
        for (int off = 16; off > 0; off >>= 1) {
            float ov = __shfl_down_sync(0xffffffffu, bv, off);
            int   oi = __shfl_down_sync(0xffffffffu, bi, off);
            if (ov > bv || (ov == bv && oi < bi)) { bv = ov; bi = oi; }
        }
        bi = __shfl_sync(0xffffffffu, bi, 0);
        if (lane == 0) g_idx[row*TOPK + k] = bi;
        if ((bi & 31) == lane) {
            const int slot = bi >> 5;
            #pragma unroll
            for (int j = 0; j < 8; j++) if (j == slot) v[j] = NEG_INF;
        }
    }
}

// ---------------------------------------------------------------------------
// Type logits: hidden = tanh(P[row] + Q[head]);  out = hidden @ fc_w^T + fc_b
// ---------------------------------------------------------------------------
__global__ __launch_bounds__(128) void typelogits_kernel(
    const float* __restrict__ fw, const float* __restrict__ fb,
    float* __restrict__ out)
{
    const int row  = blockIdx.x;
    const int m    = threadIdx.x >> 5;
    const int lane = threadIdx.x & 31;
    const int b    = row >> 8;

    const int hidx = g_idx[row*TOPK + m];
    const float* Prow = g_P + (size_t)row * HD;
    const float* Qrow = g_Q + (size_t)(b*SEQ + hidx) * HD;

    float a0=0.f, a1=0.f, a2=0.f, a3=0.f;
    for (int h = lane; h < HD; h += 32) {
        const float t = tanh_acc(Prow[h] + Qrow[h]);
        a0 = fmaf(t, fw[h       ], a0);
        a1 = fmaf(t, fw[h +   HD], a1);
        a2 = fmaf(t, fw[h + 2*HD], a2);
        a3 = fmaf(t, fw[h + 3*HD], a3);
    }
    #pragma unroll
    for (int off = 16; off > 0; off >>= 1) {
        a0 += __shfl_down_sync(0xffffffffu, a0, off);
        a1 += __shfl_down_sync(0xffffffffu, a1, off);
        a2 += __shfl_down_sync(0xffffffffu, a2, off);
        a3 += __shfl_down_sync(0xffffffffu, a3, off);
    }
    if (lane == 0) {
        float* o = out + LOGITS_SZ + (size_t)(row*TOPK + m) * NL;
        o[0] = a0 + fb[0];
        o[1] = a1 + fb[1];
        o[2] = a2 + fb[2];
        o[3] = a3 + fb[3];
    }
}

// ---------------------------------------------------------------------------
extern "C" void kernel_launch(void* const* d_in, const int* in_sizes, int n_in,
                              void* d_out, int out_size)
{
    const float* X   = (const float*)d_in[0];
    const float* Wa  = (const float*)d_in[1];
    const float* Wab = (const float*)d_in[2];
    const float* Ua  = (const float*)d_in[3];
    const float* Uab = (const float*)d_in[4];
    const float* va  = (const float*)d_in[5];
    const float* Dw  = (const float*)d_in[6];
    const float* Db  = (const float*)d_in[7];
    const float* fw  = (const float*)d_in[8];
    const float* fb  = (const float*)d_in[9];
    float* out = (float*)d_out;

    cudaFuncSetAttribute(gemm_mma_kernel,
                         cudaFuncAttributeMaxDynamicSharedMemorySize, GEMM_SMEM);

    splitA_kernel<<<(MROWS*HD + 255)/256, 256>>>(X);
    splitB_kernel<<<(NCOLS*HD + 255)/256, 256>>>(Wa, Ua, Dw);

    dim3 gg(NCOLS/64, MROWS/128);            // 48 x 8 = 384 CTAs
    gemm_mma_kernel<<<gg, 256, GEMM_SMEM>>>(Wab, Uab, Db);

    dim3 g2(SEQ/32, SEQ/32, NB*NHCH);        // 8 x 8 x 12 = 768 CTAs
    biaffine5_kernel<<<g2, 128>>>(va);

    topk_kernel<<<MROWS/8, 256>>>(out);

    typelogits_kernel<<<MROWS, 128>>>(fw, fb, out);
}